// round 14
// baseline (speedup 1.0000x reference)
#include <cuda_runtime.h>

#define FULL 0xffffffffu
typedef unsigned long long u64;

// ---------------------------------------------------------------------------
// pitch_predictor: 4-layer biLSTM (B=128,T=2048,H=16) -> x[:,7::8,:] ->
//                  4-layer uniLSTM (H=1) -> out (128,256,1) fp32
// Per layer: parallel xW GEMM (throughput) + recurrence warps (latency).
// Recurrence v4: 2 software-interleaved batch streams per instruction stream
// (shared weights) x 2 SIMT halves = 4 recurrences/warp; stalls of one
// stream filled by the other. tanh.approx activations, packed f32x2 dots.
// ---------------------------------------------------------------------------

__device__ float g_xw[128 * 2 * 2048 * 64];  // preacts (bias folded): slot = u*4 + gate
__device__ float g_hA[128 * 2048 * 32];      // inter-layer h ping
__device__ float g_hB[128 * 2048 * 32];      // inter-layer h pong
__device__ float g_unixw[128 * 256 * 4];
__device__ float g_unih[256 * 128];

// ---------------- activations ----------------------------------------------
__device__ __forceinline__ float tanh_fast(float x) {
    float y; asm("tanh.approx.f32 %0, %1;" : "=f"(y) : "f"(x)); return y;
}
__device__ __forceinline__ float sigm_fast(float x) {
    return fmaf(0.5f, tanh_fast(0.5f * x), 0.5f);
}

// ---------------- packed f32x2 helpers --------------------------------------
__device__ __forceinline__ u64 pack2(float lo, float hi) {
    u64 r; asm("mov.b64 %0, {%1, %2};" : "=l"(r) : "f"(lo), "f"(hi)); return r;
}
__device__ __forceinline__ void unpack2(u64 v, float& lo, float& hi) {
    asm("mov.b64 {%0, %1}, %2;" : "=f"(lo), "=f"(hi) : "l"(v));
}
__device__ __forceinline__ u64 fma2(u64 a, u64 b, u64 c) {
    u64 d; asm("fma.rn.f32x2 %0, %1, %2, %3;" : "=l"(d) : "l"(a), "l"(b), "l"(c)); return d;
}
__device__ __forceinline__ u64 add2(u64 a, u64 b) {
    u64 d; asm("add.rn.f32x2 %0, %1, %2;" : "=l"(d) : "l"(a), "l"(b)); return d;
}

// ---------------------------------------------------------------------------
// xW GEMM. Output row per (b,dir,t): 64 floats, slot = u*4 + q
// (q = 0:i 1:f 2:g 3:o), so lane u's 4 preacts are one contiguous float4.
// thread tid = d*64 + q*16 + u. grid.x = 128 batches * 8 t-chunks (256 t).
// SRC: 0 external x, 1 g_hA, 2 g_hB.
// ---------------------------------------------------------------------------
template <int IN, int SRC>
__global__ void __launch_bounds__(128)
xw_gemm_kernel(const float* __restrict__ xparam,
               const float* __restrict__ Wih,    // [2][64][IN]
               const float* __restrict__ bias)   // [2][64]
{
    const float* __restrict__ xin =
        (SRC == 0) ? xparam : (SRC == 1 ? g_hA : g_hB);

    const int b  = blockIdx.x >> 3;
    const int t0 = (blockIdx.x & 7) * 256;
    const int tid = threadIdx.x;
    const int d = tid >> 6;
    const int q = (tid >> 4) & 3;
    const int u = tid & 15;
    const int g = q * 16 + u;
    const int slot = u * 4 + q;

    u64 w2[IN / 2];
    {
        const float* wr = Wih + (d * 64 + g) * IN;
#pragma unroll
        for (int k = 0; k < IN / 2; k++) w2[k] = pack2(wr[2 * k], wr[2 * k + 1]);
    }
    const float bs = bias[d * 64 + g];

    __shared__ float xs[128 * IN];
    float* __restrict__ gout =
        g_xw + (size_t)((b * 2 + d) * 2048) * 64 + slot;

    for (int cc = 0; cc < 2; ++cc) {
        const int tb = t0 + cc * 128;
        __syncthreads();
        const float4* src = (const float4*)(xin + (size_t)(b * 2048 + tb) * IN);
        float4* dst = (float4*)xs;
        for (int i = tid; i < 128 * IN / 4; i += 128) dst[i] = src[i];
        __syncthreads();

#pragma unroll 2
        for (int tt = 0; tt < 128; ++tt) {
            const float4* xr = (const float4*)(xs + tt * IN);
            u64 acc_a = pack2(bs, 0.0f);
            u64 acc_b = pack2(0.0f, 0.0f);
#pragma unroll
            for (int k4 = 0; k4 < IN / 4; k4++) {
                float4 xv = xr[k4];
                acc_a = fma2(pack2(xv.x, xv.y), w2[k4 * 2],     acc_a);
                acc_b = fma2(pack2(xv.z, xv.w), w2[k4 * 2 + 1], acc_b);
            }
            float a0, a1, b0, b1;
            unpack2(acc_a, a0, a1);
            unpack2(acc_b, b0, b1);
            gout[(size_t)(tb + tt) * 64] = (a0 + b0) + (a1 + b1);
        }
    }
}

// ---------------------------------------------------------------------------
// Recurrence v4: 64 blocks x 32 threads (1 warp/SM).
// warp w: dir = w>>5, p = w&31 -> batches 4p..4p+3, one direction.
// Lanes 0-15: batches 4p (stream A), 4p+1 (stream B).
// Lanes 16-31: batches 4p+2 (A), 4p+3 (B) — same SIMT instructions.
// Lane u owns all 4 gates of h-element u; weights shared by both streams.
// DST: 1 -> g_hA, 2 -> g_hB.
// ---------------------------------------------------------------------------
template <int DST>
__global__ void __launch_bounds__(32, 1)
rec_kernel(const float* __restrict__ Whh_base)   // [2][64][16] for this layer
{
    const int lane = threadIdx.x;
    const int u    = lane & 15;
    const int half = lane >> 4;
    const int w    = blockIdx.x;
    const int dir  = w >> 5;
    const int p    = w & 31;
    const int bA   = p * 4 + half * 2;
    const int bB   = bA + 1;

    const float* __restrict__ Whh = Whh_base + dir * 64 * 16;

    u64 wif2[16], wgo2[16];
#pragma unroll
    for (int j = 0; j < 16; j++) {
        wif2[j] = pack2(Whh[(u)      * 16 + j], Whh[(16 + u) * 16 + j]);
        wgo2[j] = pack2(Whh[(32 + u) * 16 + j], Whh[(48 + u) * 16 + j]);
    }

    const int dt     = dir ? -1 : 1;
    const int tstart = dir ? 2047 : 0;

    const float4* __restrict__ xpA =
        (const float4*)(g_xw + (size_t)((bA * 2 + dir) * 2048) * 64) + u;
    const float4* __restrict__ xpB =
        (const float4*)(g_xw + (size_t)((bB * 2 + dir) * 2048) * 64) + u;
    float* __restrict__ outbase = (DST == 1 ? g_hA : g_hB);
    float* __restrict__ outA = outbase + (size_t)bA * 2048 * 32 + dir * 16 + u;
    float* __restrict__ outB = outbase + (size_t)bB * 2048 * 32 + dir * 16 + u;

    float hA = 0.0f, cA = 0.0f, hB = 0.0f, cB = 0.0f;

    float4 bufA[4], bufB[4];
#pragma unroll
    for (int i = 0; i < 4; i++) {
        bufA[i] = __ldg(&xpA[(size_t)(tstart + i * dt) * 16]);
        bufB[i] = __ldg(&xpB[(size_t)(tstart + i * dt) * 16]);
    }

    int t  = tstart;
    int tl = tstart + 4 * dt;

    for (int s = 0; s < 2048; s += 4) {
        const bool pf = (s + 4 < 2048);
#pragma unroll
        for (int i = 0; i < 4; i++) {
            float4 xwA = bufA[i];
            float4 xwB = bufB[i];
            if (pf) {
                bufA[i] = __ldg(&xpA[(size_t)tl * 16]);
                bufB[i] = __ldg(&xpB[(size_t)tl * 16]);
                tl += dt;
            }

            // interleaved packed recurrent dots for both streams
            u64 Aif0 = pack2(xwA.x, xwA.y), Aif1 = pack2(0.f, 0.f);
            u64 Ago0 = pack2(xwA.z, xwA.w), Ago1 = pack2(0.f, 0.f);
            u64 Bif0 = pack2(xwB.x, xwB.y), Bif1 = pack2(0.f, 0.f);
            u64 Bgo0 = pack2(xwB.z, xwB.w), Bgo1 = pack2(0.f, 0.f);
#pragma unroll
            for (int j = 0; j < 16; j += 2) {
                float a0 = __shfl_sync(FULL, hA, j,     16);
                float a1 = __shfl_sync(FULL, hA, j + 1, 16);
                float b0 = __shfl_sync(FULL, hB, j,     16);
                float b1 = __shfl_sync(FULL, hB, j + 1, 16);
                u64 pa0 = pack2(a0, a0), pa1 = pack2(a1, a1);
                u64 pb0 = pack2(b0, b0), pb1 = pack2(b1, b1);
                Aif0 = fma2(pa0, wif2[j],     Aif0);
                Aif1 = fma2(pa1, wif2[j + 1], Aif1);
                Ago0 = fma2(pa0, wgo2[j],     Ago0);
                Ago1 = fma2(pa1, wgo2[j + 1], Ago1);
                Bif0 = fma2(pb0, wif2[j],     Bif0);
                Bif1 = fma2(pb1, wif2[j + 1], Bif1);
                Bgo0 = fma2(pb0, wgo2[j],     Bgo0);
                Bgo1 = fma2(pb1, wgo2[j + 1], Bgo1);
            }
            float Ai, Af, Ag, Ao, Bi, Bf, Bg, Bo;
            unpack2(add2(Aif0, Aif1), Ai, Af);
            unpack2(add2(Ago0, Ago1), Ag, Ao);
            unpack2(add2(Bif0, Bif1), Bi, Bf);
            unpack2(add2(Bgo0, Bgo1), Bg, Bo);

            // stream A epilogue (B's issues fill A's MUFU latencies)
            float Atg = tanh_fast(Ag);
            float Asi = sigm_fast(Ai);
            float Asf = sigm_fast(Af);
            float Aso = sigm_fast(Ao);
            float Btg = tanh_fast(Bg);
            float Bsi = sigm_fast(Bi);
            float Bsf = sigm_fast(Bf);
            float Bso = sigm_fast(Bo);

            cA = fmaf(Asf, cA, Asi * Atg);
            cB = fmaf(Bsf, cB, Bsi * Btg);
            hA = Aso * tanh_fast(cA);
            hB = Bso * tanh_fast(cB);

            outA[(size_t)t * 32] = hA;
            outB[(size_t)t * 32] = hB;
            t += dt;
        }
    }
}

// ---------------------------------------------------------------------------
// uni-LSTM layer-0 input projection on downsampled biLSTM output (g_hB).
// ---------------------------------------------------------------------------
__global__ void uni_xw_kernel(const float* __restrict__ uWih0,  // [4][32]
                              const float* __restrict__ ub)     // [4][4]
{
    int idx = blockIdx.x * blockDim.x + threadIdx.x;  // 0..32767
    if (idx >= 128 * 256) return;
    int b  = idx >> 8;
    int tt = idx & 255;
    const float* __restrict__ xr = g_hB + (size_t)(b * 2048 + (tt * 8 + 7)) * 32;
    float x[32];
#pragma unroll
    for (int k = 0; k < 32; k++) x[k] = xr[k];
#pragma unroll
    for (int g = 0; g < 4; g++) {
        float acc = __ldg(&ub[g]);
#pragma unroll
        for (int k = 0; k < 32; k++) acc = fmaf(x[k], __ldg(&uWih0[g * 32 + k]), acc);
        g_unixw[idx * 4 + g] = acc;
    }
}

// ---------------------------------------------------------------------------
// 4-layer unidirectional LSTM, H=1. One thread per batch.
// ---------------------------------------------------------------------------
__global__ void uni_rec_kernel(const float* __restrict__ uWih,  // [3][4][1]
                               const float* __restrict__ uWhh,  // [4][4][1]
                               const float* __restrict__ ub,    // [4][4]
                               float* __restrict__ outp)        // [128][256]
{
    int b = blockIdx.x * blockDim.x + threadIdx.x;
    if (b >= 128) return;

    {
        float h = 0.f, c = 0.f;
        const float w0 = uWhh[0], w1 = uWhh[1], w2 = uWhh[2], w3 = uWhh[3];
        const float4* xwp = (const float4*)(g_unixw) + b * 256;
        for (int t = 0; t < 256; t++) {
            float4 xw = xwp[t];
            float gi = fmaf(h, w0, xw.x);
            float gf = fmaf(h, w1, xw.y);
            float gg = fmaf(h, w2, xw.z);
            float go = fmaf(h, w3, xw.w);
            c = fmaf(sigm_fast(gf), c, sigm_fast(gi) * tanh_fast(gg));
            h = sigm_fast(go) * tanh_fast(c);
            g_unih[t * 128 + b] = h;
        }
    }
    for (int l = 1; l < 4; l++) {
        const float* wih = uWih + (l - 1) * 4;
        const float* whh = uWhh + l * 4;
        const float* bb  = ub + l * 4;
        const float vi0 = wih[0], vi1 = wih[1], vi2 = wih[2], vi3 = wih[3];
        const float w0 = whh[0], w1 = whh[1], w2 = whh[2], w3 = whh[3];
        const float c0 = bb[0], c1 = bb[1], c2 = bb[2], c3 = bb[3];
        float h = 0.f, c = 0.f;
        for (int t = 0; t < 256; t++) {
            float xx = g_unih[t * 128 + b];
            float gi = fmaf(h, w0, fmaf(xx, vi0, c0));
            float gf = fmaf(h, w1, fmaf(xx, vi1, c1));
            float gg = fmaf(h, w2, fmaf(xx, vi2, c2));
            float go = fmaf(h, w3, fmaf(xx, vi3, c3));
            c = fmaf(sigm_fast(gf), c, sigm_fast(gi) * tanh_fast(gg));
            h = sigm_fast(go) * tanh_fast(c);
            if (l == 3) outp[b * 256 + t] = h;
            else        g_unih[t * 128 + b] = h;
        }
    }
}

// ---------------------------------------------------------------------------
extern "C" void kernel_launch(void* const* d_in, const int* in_sizes, int n_in,
                              void* d_out, int out_size)
{
    const float* x     = (const float*)d_in[0];  // (128,2048,24)
    const float* bWih0 = (const float*)d_in[1];  // (2,64,24)
    const float* bWih  = (const float*)d_in[2];  // (3,2,64,32)
    const float* bWhh  = (const float*)d_in[3];  // (4,2,64,16)
    const float* bb    = (const float*)d_in[4];  // (4,2,64)
    const float* uWih0 = (const float*)d_in[5];  // (4,32)
    const float* uWih  = (const float*)d_in[6];  // (3,4,1)
    const float* uWhh  = (const float*)d_in[7];  // (4,4,1)
    const float* ub    = (const float*)d_in[8];  // (4,4)
    float* out = (float*)d_out;                  // (128,256,1)

    dim3 ggrid(1024), gblock(128);
    dim3 rgrid(64), rblock(32);

    // layer 0
    xw_gemm_kernel<24, 0><<<ggrid, gblock>>>(x, bWih0, bb + 0 * 128);
    rec_kernel<1><<<rgrid, rblock>>>(bWhh + 0 * 2 * 64 * 16);           // -> g_hA
    // layer 1
    xw_gemm_kernel<32, 1><<<ggrid, gblock>>>(nullptr, bWih + 0 * 2 * 64 * 32, bb + 1 * 128);
    rec_kernel<2><<<rgrid, rblock>>>(bWhh + 1 * 2 * 64 * 16);           // -> g_hB
    // layer 2
    xw_gemm_kernel<32, 2><<<ggrid, gblock>>>(nullptr, bWih + 1 * 2 * 64 * 32, bb + 2 * 128);
    rec_kernel<1><<<rgrid, rblock>>>(bWhh + 2 * 2 * 64 * 16);           // -> g_hA
    // layer 3
    xw_gemm_kernel<32, 1><<<ggrid, gblock>>>(nullptr, bWih + 2 * 2 * 64 * 32, bb + 3 * 128);
    rec_kernel<2><<<rgrid, rblock>>>(bWhh + 3 * 2 * 64 * 16);           // -> g_hB

    // uni-LSTM stack
    uni_xw_kernel<<<128, 256>>>(uWih0, ub);
    uni_rec_kernel<<<4, 32>>>(uWih, uWhh, ub, out);
}